// round 3
// baseline (speedup 1.0000x reference)
#include <cuda_runtime.h>
#include <cuda_bf16.h>
#include <cstdint>

// Problem constants
#define B_    32
#define C_    256
#define H_    64
#define W_    64
#define HW_   4096          // H_*W_
#define NE_   1024          // codebook entries
#define ED_   256           // embedding dim
#define NPOS_ 131072        // B_*H_*W_
#define MT_   128           // positions per block
#define NBLK_ (NPOS_ / MT_) // 1024 blocks

#define ZQ_ELEMS_ 33554432                 // B_*C_*HW_
#define CB_ELEMS_ (NE_ * ED_)              // 262144
#define LOSS_OFF_ ((size_t)ZQ_ELEMS_)      // 33554432
#define CLS_OFF_  (LOSS_OFF_ + 1)
#define IDX_OFF_  (LOSS_OFF_ + 2)

// Scratch (no allocation allowed in kernel_launch)
__device__ float g_ctb[ED_ * NE_];   // transposed codebook: ctb[c*NE_ + n]
__device__ float g_cnorm[NE_];       // 0.5 * ||e_n||^2
__device__ float g_part[NBLK_];      // per-block loss partials

// ---------------------------------------------------------------------------
// Kernel 1: transpose codebook + half-norms. grid=NE_, block=256 (one code/blk)
// ---------------------------------------------------------------------------
__global__ void vq_prep(const float* __restrict__ cb) {
    const int n = blockIdx.x;      // code index
    const int c = threadIdx.x;     // channel
    float v = cb[n * ED_ + c];
    g_ctb[c * NE_ + n] = v;

    float s = v * v;
    #pragma unroll
    for (int o = 16; o; o >>= 1) s += __shfl_xor_sync(0xFFFFFFFFu, s, o);
    __shared__ float red[8];
    if ((c & 31) == 0) red[c >> 5] = s;
    __syncthreads();
    if (c == 0) {
        float t = 0.f;
        #pragma unroll
        for (int i = 0; i < 8; i++) t += red[i];
        g_cnorm[n] = 0.5f * t;
    }
}

// ---------------------------------------------------------------------------
// Kernel 2: fused distance-GEMM + argmin + gather + loss partial.
// grid = NBLK_ (1024), block = 256.
// Each block: 128 consecutive flat positions (never crosses a batch boundary:
// HW_=4096 is a multiple of MT_=128), all 1024 codes.
// ---------------------------------------------------------------------------
__global__ void __launch_bounds__(256, 2)
vq_main(const float* __restrict__ z, const float* __restrict__ cb,
        float* __restrict__ out) {
    __shared__ union SMem {
        struct { float As[2][8][MT_]; float Bs[2][8][128]; } g;  // 16 KB
        struct { float val[MT_][17]; int idx[MT_][17]; } f;      // ~17.4 KB
    } sm;
    __shared__ int   sBest[MT_];
    __shared__ float sRed[8];

    const int tid  = threadIdx.x;
    const int blk  = blockIdx.x;
    const int pos0 = blk * MT_;
    const int b    = pos0 >> 12;          // / HW_
    const int hw0  = pos0 & (HW_ - 1);    // multiple of 128
    const float* zb = z + (size_t)b * C_ * HW_ + hw0;  // zb[c*HW_ + m]

    const int tm = tid & 15;   // 16 row-groups of 8
    const int tn = tid >> 4;   // 16 col-groups of 8

    float bestVal[8];
    int   bestIdx[8];
    #pragma unroll
    for (int i = 0; i < 8; i++) { bestVal[i] = 3.4e38f; bestIdx[i] = 0; }

    for (int nt = 0; nt < 8; ++nt) {          // 8 tiles of 128 codes
        float acc[8][8];
        #pragma unroll
        for (int i = 0; i < 8; i++)
            #pragma unroll
            for (int j = 0; j < 8; j++) acc[i][j] = 0.f;

        // Preload k-stage 0
        #pragma unroll
        for (int j = 0; j < 4; j++) {
            int q = tid + 256 * j;        // 0..1023
            int k = q >> 7, m = q & 127;
            sm.g.As[0][k][m] = zb[k * HW_ + m];
            sm.g.Bs[0][k][m] = g_ctb[k * NE_ + nt * 128 + m];
        }
        __syncthreads();

        #pragma unroll 1
        for (int k0 = 0; k0 < ED_; k0 += 8) {
            const int cur = (k0 >> 3) & 1;
            float ra[4], rb[4];
            const bool more = (k0 + 8 < ED_);
            if (more) {
                #pragma unroll
                for (int j = 0; j < 4; j++) {
                    int q = tid + 256 * j;
                    int k = q >> 7, m = q & 127;
                    ra[j] = zb[(k0 + 8 + k) * HW_ + m];
                    rb[j] = g_ctb[(k0 + 8 + k) * NE_ + nt * 128 + m];
                }
            }
            // Compute current stage
            #pragma unroll
            for (int kk = 0; kk < 8; ++kk) {
                float a[8], bv[8];
                float4 t;
                t = *(const float4*)&sm.g.As[cur][kk][tm * 8];
                a[0]=t.x; a[1]=t.y; a[2]=t.z; a[3]=t.w;
                t = *(const float4*)&sm.g.As[cur][kk][tm * 8 + 4];
                a[4]=t.x; a[5]=t.y; a[6]=t.z; a[7]=t.w;
                t = *(const float4*)&sm.g.Bs[cur][kk][tn * 8];
                bv[0]=t.x; bv[1]=t.y; bv[2]=t.z; bv[3]=t.w;
                t = *(const float4*)&sm.g.Bs[cur][kk][tn * 8 + 4];
                bv[4]=t.x; bv[5]=t.y; bv[6]=t.z; bv[7]=t.w;
                #pragma unroll
                for (int i = 0; i < 8; i++)
                    #pragma unroll
                    for (int j = 0; j < 8; j++)
                        acc[i][j] = fmaf(a[i], bv[j], acc[i][j]);
            }
            if (more) {
                const int nxt = cur ^ 1;
                #pragma unroll
                for (int j = 0; j < 4; j++) {
                    int q = tid + 256 * j;
                    int k = q >> 7, m = q & 127;
                    sm.g.As[nxt][k][m] = ra[j];
                    sm.g.Bs[nxt][k][m] = rb[j];
                }
            }
            __syncthreads();
        }

        // dist_half(n) = 0.5||e||^2 - z.e ; argmin equals full-L2 argmin.
        // n increases monotonically across nt and j, strict '<' keeps first min.
        #pragma unroll
        for (int j = 0; j < 8; j++) {
            const int n = nt * 128 + tn * 8 + j;
            const float cn = g_cnorm[n];
            #pragma unroll
            for (int i = 0; i < 8; i++) {
                float d = cn - acc[i][j];
                if (d < bestVal[i]) { bestVal[i] = d; bestIdx[i] = n; }
            }
        }
        // k-loop ended with __syncthreads(); smem reuse for next nt is safe.
    }

    // Cross-thread argmin reduction (16 candidates per row), tie -> lowest idx
    #pragma unroll
    for (int i = 0; i < 8; i++) {
        const int row = tm * 8 + i;
        sm.f.val[row][tn] = bestVal[i];
        sm.f.idx[row][tn] = bestIdx[i];
    }
    __syncthreads();
    if (tid < MT_) {
        float bv = sm.f.val[tid][0];
        int   bi = sm.f.idx[tid][0];
        #pragma unroll
        for (int j = 1; j < 16; j++) {
            float v = sm.f.val[tid][j];
            int   ix = sm.f.idx[tid][j];
            if (v < bv || (v == bv && ix < bi)) { bv = v; bi = ix; }
        }
        sBest[tid] = bi;
        out[IDX_OFF_ + pos0 + tid] = (float)bi;   // indices as output dtype
    }
    __syncthreads();

    // Gather z_q (coalesced writes along hw) + fused loss partial
    const int m  = tid & 127;
    const int c0 = tid >> 7;                 // 0 or 1
    const int bi = sBest[m];
    const float* crow = cb + (size_t)bi * ED_;
    float* ob = out + (size_t)b * C_ * HW_ + hw0;
    float lsum = 0.f;
    #pragma unroll 4
    for (int c = c0; c < ED_; c += 2) {
        float q  = crow[c];                  // scattered 4B reads, L2-resident
        float zv = zb[c * HW_ + m];
        ob[c * HW_ + m] = q;
        float df = q - zv;
        lsum = fmaf(df, df, lsum);
    }
    #pragma unroll
    for (int o = 16; o; o >>= 1) lsum += __shfl_xor_sync(0xFFFFFFFFu, lsum, o);
    if ((tid & 31) == 0) sRed[tid >> 5] = lsum;
    __syncthreads();
    if (tid == 0) {
        float t = 0.f;
        #pragma unroll
        for (int i = 0; i < 8; i++) t += sRed[i];
        g_part[blk] = t;   // deterministic: no float atomics
    }
}

// ---------------------------------------------------------------------------
// Kernel 3: reduce loss partials, write scalars. 1 block, 256 threads.
// ---------------------------------------------------------------------------
__global__ void vq_loss(float* __restrict__ out) {
    __shared__ double red[256];
    const int tid = threadIdx.x;
    double s = 0.0;
    for (int i = tid; i < NBLK_; i += 256) s += (double)g_part[i];
    red[tid] = s;
    __syncthreads();
    for (int o = 128; o; o >>= 1) {
        if (tid < o) red[tid] += red[tid + o];
        __syncthreads();
    }
    if (tid == 0) {
        out[LOSS_OFF_] = (float)(red[0] / (double)ZQ_ELEMS_);
        out[CLS_OFF_]  = 0.0f;
    }
}

// ---------------------------------------------------------------------------
extern "C" void kernel_launch(void* const* d_in, const int* in_sizes, int n_in,
                              void* d_out, int out_size) {
    // Defensive input resolution by element count (z: 33554432, cb: 262144).
    const float* z  = (const float*)d_in[0];
    const float* cb = (const float*)d_in[1];
    if (n_in >= 2 && in_sizes[0] == CB_ELEMS_ && in_sizes[1] == ZQ_ELEMS_) {
        z  = (const float*)d_in[1];
        cb = (const float*)d_in[0];
    }
    float* out = (float*)d_out;                // [z_q | loss | cls | indices]

    vq_prep<<<NE_, 256>>>(cb);
    vq_main<<<NBLK_, 256>>>(z, cb, out);
    vq_loss<<<1, 256>>>(out);
}

// round 4
// speedup vs baseline: 1.0011x; 1.0011x over previous
#include <cuda_runtime.h>
#include <cuda_bf16.h>
#include <cstdint>

// Problem constants
#define B_    32
#define C_    256
#define H_    64
#define W_    64
#define HW_   4096          // H_*W_
#define NE_   1024          // codebook entries
#define ED_   256           // embedding dim
#define NPOS_ 131072        // B_*H_*W_
#define MT_   128           // positions per block
#define NBLK_ (NPOS_ / MT_) // 1024 blocks

#define ZQ_ELEMS_ 33554432                 // B_*C_*HW_
#define CB_ELEMS_ (NE_ * ED_)              // 262144
#define LOSS_OFF_ ((size_t)ZQ_ELEMS_)      // 33554432
#define CLS_OFF_  (LOSS_OFF_ + 1)
#define IDX_OFF_  (LOSS_OFF_ + 2)

// Scratch (no allocation allowed in kernel_launch)
__device__ float g_ctb[ED_ * NE_];   // transposed codebook: ctb[c*NE_ + n]
__device__ float g_cnorm[NE_];       // 0.5 * ||e_n||^2
__device__ float g_part[NBLK_];      // per-block loss partials

// ---------------------------------------------------------------------------
// Kernel 1: transpose codebook + half-norms. grid=NE_, block=256 (one code/blk)
// ---------------------------------------------------------------------------
__global__ void vq_prep(const float* __restrict__ cb) {
    const int n = blockIdx.x;      // code index
    const int c = threadIdx.x;     // channel
    float v = cb[n * ED_ + c];
    g_ctb[c * NE_ + n] = v;

    float s = v * v;
    #pragma unroll
    for (int o = 16; o; o >>= 1) s += __shfl_xor_sync(0xFFFFFFFFu, s, o);
    __shared__ float red[8];
    if ((c & 31) == 0) red[c >> 5] = s;
    __syncthreads();
    if (c == 0) {
        float t = 0.f;
        #pragma unroll
        for (int i = 0; i < 8; i++) t += red[i];
        g_cnorm[n] = 0.5f * t;
    }
}

// ---------------------------------------------------------------------------
// Kernel 2: fused distance-GEMM + argmin + gather + loss partial.
// grid = NBLK_ (1024), block = 256.
// Each block: 128 consecutive flat positions (never crosses a batch boundary:
// HW_=4096 is a multiple of MT_=128), all 1024 codes.
// ---------------------------------------------------------------------------
__global__ void __launch_bounds__(256, 2)
vq_main(const float* __restrict__ z, const float* __restrict__ cb,
        float* __restrict__ out) {
    __shared__ union SMem {
        struct { float As[2][8][MT_]; float Bs[2][8][128]; } g;  // 16 KB
        struct { float val[MT_][17]; int idx[MT_][17]; } f;      // ~17.4 KB
    } sm;
    __shared__ int   sBest[MT_];
    __shared__ float sRed[8];

    const int tid  = threadIdx.x;
    const int blk  = blockIdx.x;
    const int pos0 = blk * MT_;
    const int b    = pos0 >> 12;          // / HW_
    const int hw0  = pos0 & (HW_ - 1);    // multiple of 128
    const float* zb = z + (size_t)b * C_ * HW_ + hw0;  // zb[c*HW_ + m]

    const int tm = tid & 15;   // 16 row-groups of 8
    const int tn = tid >> 4;   // 16 col-groups of 8

    float bestVal[8];
    int   bestIdx[8];
    #pragma unroll
    for (int i = 0; i < 8; i++) { bestVal[i] = 3.4e38f; bestIdx[i] = 0; }

    for (int nt = 0; nt < 8; ++nt) {          // 8 tiles of 128 codes
        float acc[8][8];
        #pragma unroll
        for (int i = 0; i < 8; i++)
            #pragma unroll
            for (int j = 0; j < 8; j++) acc[i][j] = 0.f;

        // Preload k-stage 0
        #pragma unroll
        for (int j = 0; j < 4; j++) {
            int q = tid + 256 * j;        // 0..1023
            int k = q >> 7, m = q & 127;
            sm.g.As[0][k][m] = zb[k * HW_ + m];
            sm.g.Bs[0][k][m] = g_ctb[k * NE_ + nt * 128 + m];
        }
        __syncthreads();

        #pragma unroll 1
        for (int k0 = 0; k0 < ED_; k0 += 8) {
            const int cur = (k0 >> 3) & 1;
            float ra[4], rb[4];
            const bool more = (k0 + 8 < ED_);
            if (more) {
                #pragma unroll
                for (int j = 0; j < 4; j++) {
                    int q = tid + 256 * j;
                    int k = q >> 7, m = q & 127;
                    ra[j] = zb[(k0 + 8 + k) * HW_ + m];
                    rb[j] = g_ctb[(k0 + 8 + k) * NE_ + nt * 128 + m];
                }
            }
            // Compute current stage
            #pragma unroll
            for (int kk = 0; kk < 8; ++kk) {
                float a[8], bv[8];
                float4 t;
                t = *(const float4*)&sm.g.As[cur][kk][tm * 8];
                a[0]=t.x; a[1]=t.y; a[2]=t.z; a[3]=t.w;
                t = *(const float4*)&sm.g.As[cur][kk][tm * 8 + 4];
                a[4]=t.x; a[5]=t.y; a[6]=t.z; a[7]=t.w;
                t = *(const float4*)&sm.g.Bs[cur][kk][tn * 8];
                bv[0]=t.x; bv[1]=t.y; bv[2]=t.z; bv[3]=t.w;
                t = *(const float4*)&sm.g.Bs[cur][kk][tn * 8 + 4];
                bv[4]=t.x; bv[5]=t.y; bv[6]=t.z; bv[7]=t.w;
                #pragma unroll
                for (int i = 0; i < 8; i++)
                    #pragma unroll
                    for (int j = 0; j < 8; j++)
                        acc[i][j] = fmaf(a[i], bv[j], acc[i][j]);
            }
            if (more) {
                const int nxt = cur ^ 1;
                #pragma unroll
                for (int j = 0; j < 4; j++) {
                    int q = tid + 256 * j;
                    int k = q >> 7, m = q & 127;
                    sm.g.As[nxt][k][m] = ra[j];
                    sm.g.Bs[nxt][k][m] = rb[j];
                }
            }
            __syncthreads();
        }

        // dist_half(n) = 0.5||e||^2 - z.e ; argmin equals full-L2 argmin.
        // n increases monotonically across nt and j, strict '<' keeps first min.
        #pragma unroll
        for (int j = 0; j < 8; j++) {
            const int n = nt * 128 + tn * 8 + j;
            const float cn = g_cnorm[n];
            #pragma unroll
            for (int i = 0; i < 8; i++) {
                float d = cn - acc[i][j];
                if (d < bestVal[i]) { bestVal[i] = d; bestIdx[i] = n; }
            }
        }
        // k-loop ended with __syncthreads(); smem reuse for next nt is safe.
    }

    // Cross-thread argmin reduction (16 candidates per row), tie -> lowest idx
    #pragma unroll
    for (int i = 0; i < 8; i++) {
        const int row = tm * 8 + i;
        sm.f.val[row][tn] = bestVal[i];
        sm.f.idx[row][tn] = bestIdx[i];
    }
    __syncthreads();
    if (tid < MT_) {
        float bv = sm.f.val[tid][0];
        int   bi = sm.f.idx[tid][0];
        #pragma unroll
        for (int j = 1; j < 16; j++) {
            float v = sm.f.val[tid][j];
            int   ix = sm.f.idx[tid][j];
            if (v < bv || (v == bv && ix < bi)) { bv = v; bi = ix; }
        }
        sBest[tid] = bi;
        out[IDX_OFF_ + pos0 + tid] = (float)bi;   // indices as output dtype
    }
    __syncthreads();

    // Gather z_q (coalesced writes along hw) + fused loss partial
    const int m  = tid & 127;
    const int c0 = tid >> 7;                 // 0 or 1
    const int bi = sBest[m];
    const float* crow = cb + (size_t)bi * ED_;
    float* ob = out + (size_t)b * C_ * HW_ + hw0;
    float lsum = 0.f;
    #pragma unroll 4
    for (int c = c0; c < ED_; c += 2) {
        float q  = crow[c];                  // scattered 4B reads, L2-resident
        float zv = zb[c * HW_ + m];
        ob[c * HW_ + m] = q;
        float df = q - zv;
        lsum = fmaf(df, df, lsum);
    }
    #pragma unroll
    for (int o = 16; o; o >>= 1) lsum += __shfl_xor_sync(0xFFFFFFFFu, lsum, o);
    if ((tid & 31) == 0) sRed[tid >> 5] = lsum;
    __syncthreads();
    if (tid == 0) {
        float t = 0.f;
        #pragma unroll
        for (int i = 0; i < 8; i++) t += sRed[i];
        g_part[blk] = t;   // deterministic: no float atomics
    }
}

// ---------------------------------------------------------------------------
// Kernel 3: reduce loss partials, write scalars. 1 block, 256 threads.
// ---------------------------------------------------------------------------
__global__ void vq_loss(float* __restrict__ out) {
    __shared__ double red[256];
    const int tid = threadIdx.x;
    double s = 0.0;
    for (int i = tid; i < NBLK_; i += 256) s += (double)g_part[i];
    red[tid] = s;
    __syncthreads();
    for (int o = 128; o; o >>= 1) {
        if (tid < o) red[tid] += red[tid + o];
        __syncthreads();
    }
    if (tid == 0) {
        out[LOSS_OFF_] = (float)(red[0] / (double)ZQ_ELEMS_);
        out[CLS_OFF_]  = 0.0f;
    }
}

// ---------------------------------------------------------------------------
extern "C" void kernel_launch(void* const* d_in, const int* in_sizes, int n_in,
                              void* d_out, int out_size) {
    // Defensive input resolution by element count (z: 33554432, cb: 262144).
    const float* z  = (const float*)d_in[0];
    const float* cb = (const float*)d_in[1];
    if (n_in >= 2 && in_sizes[0] == CB_ELEMS_ && in_sizes[1] == ZQ_ELEMS_) {
        z  = (const float*)d_in[1];
        cb = (const float*)d_in[0];
    }
    float* out = (float*)d_out;                // [z_q | loss | cls | indices]

    vq_prep<<<NE_, 256>>>(cb);
    vq_main<<<NBLK_, 256>>>(z, cb, out);
    vq_loss<<<1, 256>>>(out);
}